// round 17
// baseline (speedup 1.0000x reference)
#include <cuda_runtime.h>
#include <cuda_bf16.h>
#include <math.h>
#include <stdint.h>

#define Bq 128
#define Sq 512
#define Tq 16
#define Eq 32
#define Hq 128
#define G3 192
#define GD 384
#define XD 160
#define Vq 32000
#define NSTEP 15

// ---------------- device scratch (static globals; no runtime alloc) -------
static __device__ float g_gi_f[(size_t)Sq * Bq * G3];
static __device__ float g_gi_b[(size_t)Sq * Bq * G3];
static __device__ float g_enc [(size_t)Bq * Sq * Hq];
static __device__ float g_encg[(size_t)Bq * Sq * Hq];
static __device__ float g_hdec[Bq * Hq];
static __device__ float g_c2  [Bq * Hq];
static __device__ __nv_bfloat16 g_W1b[(size_t)Vq * Hq];      // Wout hi
static __device__ __nv_bfloat16 g_W2b[(size_t)Vq * Hq];      // Wout lo
static __device__ __nv_bfloat16 g_H1b[(size_t)NSTEP * Bq * Hq];
static __device__ __nv_bfloat16 g_H2b[(size_t)NSTEP * Bq * Hq];

__device__ __forceinline__ float sigf(float x) { return 1.f / (1.f + __expf(-x)); }

#define MMA_BF16(d, a0, a1, a2, a3, b0, b1)                                    \
    asm volatile(                                                              \
        "mma.sync.aligned.m16n8k16.row.col.f32.bf16.bf16.f32 "                 \
        "{%0,%1,%2,%3}, {%4,%5,%6,%7}, {%8,%9}, {%0,%1,%2,%3};"                \
        : "+f"((d)[0]), "+f"((d)[1]), "+f"((d)[2]), "+f"((d)[3])               \
        : "r"(a0), "r"(a1), "r"(a2), "r"(a3), "r"(b0), "r"(b1))

// ============ 128x128 fp32 tile, 256 thr, 8x8 micro (single-buffer) =======
#define G128_PROLOG()                                                          \
    __shared__ float As[32][132];                                              \
    __shared__ float Bs[32][132];                                              \
    float acc[8][8];                                                           \
    _Pragma("unroll") for (int i = 0; i < 8; i++)                              \
        _Pragma("unroll") for (int j = 0; j < 8; j++) acc[i][j] = 0.f;         \
    const int tid = threadIdx.x;                                               \
    const int tx = tid & 15, ty = tid >> 4;

#define G128_KSTEP(AROW, BROW, K0)                                             \
    {                                                                          \
        const int k0 = (K0);                                                   \
        _Pragma("unroll") for (int jj = 0; jj < 4; jj++) {                     \
            int fid = tid + jj * 256;                                          \
            int m = fid >> 3, kq = fid & 7;                                    \
            const float* ap = (AROW);                                          \
            float4 v = *(const float4*)(ap + k0 + kq * 4);                     \
            As[kq*4+0][m] = v.x; As[kq*4+1][m] = v.y;                          \
            As[kq*4+2][m] = v.z; As[kq*4+3][m] = v.w;                          \
        }                                                                      \
        _Pragma("unroll") for (int jj = 0; jj < 4; jj++) {                     \
            int fid = tid + jj * 256;                                          \
            int n = fid >> 3, kq = fid & 7;                                    \
            const float* bp = (BROW);                                          \
            float4 v = *(const float4*)(bp + k0 + kq * 4);                     \
            Bs[kq*4+0][n] = v.x; Bs[kq*4+1][n] = v.y;                          \
            Bs[kq*4+2][n] = v.z; Bs[kq*4+3][n] = v.w;                          \
        }                                                                      \
        __syncthreads();                                                       \
        _Pragma("unroll") for (int k = 0; k < 32; k++) {                       \
            float4 a0 = *(const float4*)&As[k][ty * 4];                        \
            float4 a1 = *(const float4*)&As[k][64 + ty * 4];                   \
            float4 b0 = *(const float4*)&Bs[k][tx * 4];                        \
            float4 b1 = *(const float4*)&Bs[k][64 + tx * 4];                   \
            float av[8] = {a0.x,a0.y,a0.z,a0.w, a1.x,a1.y,a1.z,a1.w};          \
            float bv[8] = {b0.x,b0.y,b0.z,b0.w, b1.x,b1.y,b1.z,b1.w};          \
            _Pragma("unroll") for (int i = 0; i < 8; i++)                      \
                _Pragma("unroll") for (int j = 0; j < 8; j++)                  \
                    acc[i][j] += av[i] * bv[j];                                \
        }                                                                      \
        __syncthreads();                                                       \
    }

#define QROW(q) (((q) < 4) ? (ty * 4 + (q)) : (60 + ty * 4 + (q)))
#define QCOL(q) (((q) < 4) ? (tx * 4 + (q)) : (60 + tx * 4 + (q)))

// ================= K1: embedding gather + input projection ================
__global__ __launch_bounds__(256, 2) void k_gi(
    const int* __restrict__ inputs, const float* __restrict__ emb,
    const float* __restrict__ Wf, const float* __restrict__ Wb,
    const float* __restrict__ bf, const float* __restrict__ bb)
{
    __shared__ int tok[128];
    const int m0 = blockIdx.y * 128;
    const int n0 = blockIdx.x * 128;
    if (threadIdx.x < 128) {
        int r = m0 + threadIdx.x;
        tok[threadIdx.x] = inputs[(r & (Bq - 1)) * Sq + (r >> 7)];
    }
    __syncthreads();
    G128_PROLOG();
    G128_KSTEP(emb + (size_t)tok[m] * Eq,
               ((n0 + n) < G3) ? (Wf + (n0 + n) * Eq)
                               : (Wb + (n0 + n - G3) * Eq),
               0);
    #pragma unroll
    for (int i = 0; i < 8; i++) {
        int r = m0 + QROW(i);
        #pragma unroll
        for (int j = 0; j < 8; j++) {
            int col = n0 + QCOL(j);
            float v = acc[i][j];
            if (col < G3) g_gi_f[(size_t)r * G3 + col] = v + bf[col];
            else          g_gi_b[(size_t)r * G3 + (col - G3)] = v + bb[col - G3];
        }
    }
}

// ==================== K2: encoder recurrence (both dirs) ==================
__global__ __launch_bounds__(192) void k_enc(
    const float* __restrict__ Whf, const float* __restrict__ Whb,
    const float* __restrict__ bhf, const float* __restrict__ bhb)
{
    const int b   = blockIdx.x & 127;
    const int dir = blockIdx.x >> 7;
    const int g   = threadIdx.x;
    const float* Wh = dir ? Whb : Whf;
    const float* bh = dir ? bhb : bhf;
    const float* gi = dir ? g_gi_b : g_gi_f;

    __shared__ float h_sh[64];
    __shared__ float gh_sh[G3];
    __shared__ float gi_sh[G3];

    float w[64];
    #pragma unroll
    for (int k = 0; k < 64; k++) w[k] = Wh[g * 64 + k];
    const float bhg = bh[g];
    if (g < 64) h_sh[g] = 0.f;
    __syncthreads();

    int t = dir ? (Sq - 1) : 0;
    const int dt = dir ? -1 : 1;
    float gcur = gi[((size_t)t * Bq + b) * G3 + g];

    for (int it = 0; it < Sq; it++, t += dt) {
        float gnext = 0.f;
        if (it + 1 < Sq) gnext = gi[((size_t)(t + dt) * Bq + b) * G3 + g];
        float a0 = bhg, a1 = 0.f, a2 = 0.f, a3 = 0.f;
        #pragma unroll
        for (int k = 0; k < 64; k += 4) {
            a0 += h_sh[k + 0] * w[k + 0];
            a1 += h_sh[k + 1] * w[k + 1];
            a2 += h_sh[k + 2] * w[k + 2];
            a3 += h_sh[k + 3] * w[k + 3];
        }
        gh_sh[g] = (a0 + a1) + (a2 + a3);
        gi_sh[g] = gcur;
        __syncthreads();
        if (g < 64) {
            float r  = sigf(gi_sh[g] + gh_sh[g]);
            float z  = sigf(gi_sh[64 + g] + gh_sh[64 + g]);
            float n  = tanhf(gi_sh[128 + g] + r * gh_sh[128 + g]);
            float hn = (1.f - z) * n + z * h_sh[g];
            h_sh[g] = hn;
            g_enc[((size_t)b * Sq + t) * Hq + dir * 64 + g] = hn;
        }
        __syncthreads();
        gcur = gnext;
    }
    if (g < 64) g_hdec[b * Hq + dir * 64 + g] = h_sh[g];
}

// ========= K3: c2[b][h] = sn@W2^T + b1 + b2 ================================
__global__ __launch_bounds__(128) void k_c2(
    const float* __restrict__ W2, const float* __restrict__ b1,
    const float* __restrict__ b2)
{
    const int b = blockIdx.x, h = threadIdx.x;
    __shared__ float sn[128];
    sn[h] = g_hdec[b * 128 + h];
    __syncthreads();
    float a = b1[h] + b2[h];
    const float* wr = W2 + h * 128;
    #pragma unroll 8
    for (int k = 0; k < 128; k++) a += sn[k] * wr[k];
    g_c2[b * 128 + h] = a;
}

// ===== K4: sGate GEMM + gating =============================================
__global__ __launch_bounds__(256, 2) void k_gate(const float* __restrict__ W1)
{
    const int m0 = blockIdx.y * 128;
    G128_PROLOG();
    for (int kk = 0; kk < 128; kk += 32) {
        G128_KSTEP(g_enc + (size_t)(m0 + m) * Hq,
                   W1 + n * 128,
                   kk);
    }
    #pragma unroll
    for (int i = 0; i < 8; i++) {
        int r = m0 + QROW(i);
        int bb2 = r >> 9;
        #pragma unroll
        for (int j = 0; j < 8; j++) {
            int col = QCOL(j);
            float u   = acc[i][j] + g_c2[bb2 * 128 + col];
            float raw = g_enc[(size_t)r * Hq + col];
            g_encg[(size_t)r * Hq + col] = raw * sigf(u);
        }
    }
}

// ====== K5: one decoder step (attention + GRU), h state in g_hdec =========
__global__ __launch_bounds__(512) void k_dec_step(
    const float* __restrict__ emb, const int* __restrict__ targets,
    const float* __restrict__ Wihd, const float* __restrict__ Whhd,
    const float* __restrict__ bihd, const float* __restrict__ bhhd, int step)
{
    const int b = blockIdx.x;
    const int tid = threadIdx.x;
    const int lane = tid & 31, wrp = tid >> 5;
    __shared__ float hsh[128];
    __shared__ float sc[512];
    __shared__ float wred[16];
    __shared__ float red[16][132];
    __shared__ float xe[XD];
    __shared__ float gis[GD];
    __shared__ float ghs[GD];

    if (tid < 128) hsh[tid] = g_hdec[b * 128 + tid];
    __syncthreads();

    const float* eb = g_encg + (size_t)b * Sq * Hq;

    float a = 0.f;
    {
        const float4* r0 = (const float4*)(eb + (size_t)tid * 128);
        #pragma unroll
        for (int q = 0; q < 32; q++) {
            float4 v = r0[q];
            a += v.x * hsh[q*4] + v.y * hsh[q*4+1]
               + v.z * hsh[q*4+2] + v.w * hsh[q*4+3];
        }
    }
    float m = a;
    #pragma unroll
    for (int o = 16; o > 0; o >>= 1) m = fmaxf(m, __shfl_xor_sync(0xffffffffu, m, o));
    if (lane == 0) wred[wrp] = m;
    __syncthreads();
    float mx = wred[0];
    #pragma unroll
    for (int i = 1; i < 16; i++) mx = fmaxf(mx, wred[i]);

    float e = __expf(a - mx);
    sc[tid] = e;
    float s = e;
    #pragma unroll
    for (int o = 16; o > 0; o >>= 1) s += __shfl_xor_sync(0xffffffffu, s, o);
    __syncthreads();
    if (lane == 0) wred[wrp] = s;
    __syncthreads();
    float tot = 0.f;
    #pragma unroll
    for (int i = 0; i < 16; i++) tot += wred[i];
    float inv = 1.f / tot;

    float4 cacc = make_float4(0.f, 0.f, 0.f, 0.f);
    {
        const int sbase = wrp * 32;
        #pragma unroll 4
        for (int s2 = sbase; s2 < sbase + 32; s2++) {
            float4 v = *(const float4*)(eb + (size_t)s2 * 128 + lane * 4);
            float w4 = sc[s2];
            cacc.x += w4 * v.x; cacc.y += w4 * v.y;
            cacc.z += w4 * v.z; cacc.w += w4 * v.w;
        }
    }
    *(float4*)&red[wrp][lane * 4] = cacc;
    __syncthreads();
    if (tid < 128) {
        float c = 0.f;
        #pragma unroll
        for (int w2 = 0; w2 < 16; w2++) c += red[w2][tid];
        xe[tid] = c * inv;
    } else if (tid < 128 + Eq) {
        int d = tid - 128;
        int wrd = targets[b * Tq + step];
        xe[128 + d] = emb[(size_t)wrd * Eq + d];
    }
    __syncthreads();

    #pragma unroll 2
    for (int i = 0; i < 24; i++) {
        const int row = wrp * 24 + i;
        const float* wi = Wihd + (size_t)row * XD;
        const float* wh = Whhd + (size_t)row * 128;
        float ai = 0.f, cc = 0.f;
        #pragma unroll
        for (int q = 0; q < 5; q++) ai += wi[lane + q * 32] * xe[lane + q * 32];
        #pragma unroll
        for (int q = 0; q < 4; q++) cc += wh[lane + q * 32] * hsh[lane + q * 32];
        #pragma unroll
        for (int o = 16; o > 0; o >>= 1) {
            ai += __shfl_down_sync(0xffffffffu, ai, o);
            cc += __shfl_down_sync(0xffffffffu, cc, o);
        }
        if (lane == 0) { gis[row] = ai; ghs[row] = cc; }
    }
    __syncthreads();

    if (tid < 128) {
        float gi0 = gis[tid]       + bihd[tid];
        float gh0 = ghs[tid]       + bhhd[tid];
        float gi1 = gis[128 + tid] + bihd[128 + tid];
        float gh1 = ghs[128 + tid] + bhhd[128 + tid];
        float gi2 = gis[256 + tid] + bihd[256 + tid];
        float gh2 = ghs[256 + tid] + bhhd[256 + tid];
        float r = sigf(gi0 + gh0);
        float z = sigf(gi1 + gh1);
        float n = tanhf(gi2 + r * gh2);
        float hn = (1.f - z) * n + z * hsh[tid];
        g_hdec[b * 128 + tid] = hn;
        size_t idx = ((size_t)step * Bq + b) * Hq + tid;
        __nv_bfloat16 h1 = __float2bfloat16(hn);
        g_H1b[idx] = h1;
        g_H2b[idx] = __float2bfloat16(hn - __bfloat162float(h1));
    }
}

// ====== K5b: bf16x2 split of Wout ========================================
__global__ __launch_bounds__(256) void k_split_w(const float* __restrict__ Wout)
{
    size_t i = (size_t)blockIdx.x * 256 + threadIdx.x;
    if (i < (size_t)Vq * Hq) {
        float x = Wout[i];
        __nv_bfloat16 h1 = __float2bfloat16(x);
        g_W1b[i] = h1;
        g_W2b[i] = __float2bfloat16(x - __bfloat162float(h1));
    }
}

// ====== K6: logits for ONE step via bf16x2-split mma.sync =================
#define LROW 136
#define HTILE (128 * LROW)
#define SMEM_MM (4 * HTILE * 2)
__global__ __launch_bounds__(256) void k_logits_bmma(
    const float* __restrict__ bout, float* __restrict__ out, int step)
{
    extern __shared__ char smem[];
    __nv_bfloat16* Hs1 = (__nv_bfloat16*)smem;
    __nv_bfloat16* Hs2 = Hs1 + HTILE;
    __nv_bfloat16* Ws1 = Hs2 + HTILE;
    __nv_bfloat16* Ws2 = Ws1 + HTILE;

    const int tid = threadIdx.x;
    const int lane = tid & 31, wrp = tid >> 5;
    const int wm = wrp & 1, wn = wrp >> 1;
    const int gr = lane >> 2, tg = lane & 3;
    const int m0 = step * 128;
    const int n0 = blockIdx.x * 128;

    #pragma unroll
    for (int j = 0; j < 8; j++) {
        int fid = tid + j * 256;
        int row = fid >> 4, c = fid & 15;
        *(uint4*)&Hs1[row * LROW + c * 8] = ((const uint4*)&g_H1b[(size_t)(m0 + row) * Hq])[c];
        *(uint4*)&Hs2[row * LROW + c * 8] = ((const uint4*)&g_H2b[(size_t)(m0 + row) * Hq])[c];
        *(uint4*)&Ws1[row * LROW + c * 8] = ((const uint4*)&g_W1b[(size_t)(n0 + row) * Hq])[c];
        *(uint4*)&Ws2[row * LROW + c * 8] = ((const uint4*)&g_W2b[(size_t)(n0 + row) * Hq])[c];
    }
    __syncthreads();

    float acc[4][4][4];
    #pragma unroll
    for (int i = 0; i < 4; i++)
        #pragma unroll
        for (int j = 0; j < 4; j++)
            #pragma unroll
            for (int q = 0; q < 4; q++) acc[i][j][q] = 0.f;

    #pragma unroll
    for (int kk = 0; kk < 128; kk += 16) {
        uint32_t bh[4][2], bl[4][2];
        #pragma unroll
        for (int nt = 0; nt < 4; nt++) {
            int nr = (wn * 32 + nt * 8 + gr) * LROW + kk + 2 * tg;
            bh[nt][0] = *(const uint32_t*)&Ws1[nr];
            bh[nt][1] = *(const uint32_t*)&Ws1[nr + 8];
            bl[nt][0] = *(const uint32_t*)&Ws2[nr];
            bl[nt][1] = *(const uint32_t*)&Ws2[nr + 8];
        }
        #pragma unroll
        for (int mt = 0; mt < 4; mt++) {
            int mr = (wm * 64 + mt * 16 + gr) * LROW + kk + 2 * tg;
            uint32_t ah0 = *(const uint32_t*)&Hs1[mr];
            uint32_t ah1 = *(const uint32_t*)&Hs1[mr + 8 * LROW];
            uint32_t ah2 = *(const uint32_t*)&Hs1[mr + 8];
            uint32_t ah3 = *(const uint32_t*)&Hs1[mr + 8 * LROW + 8];
            uint32_t al0 = *(const uint32_t*)&Hs2[mr];
            uint32_t al1 = *(const uint32_t*)&Hs2[mr + 8 * LROW];
            uint32_t al2 = *(const uint32_t*)&Hs2[mr + 8];
            uint32_t al3 = *(const uint32_t*)&Hs2[mr + 8 * LROW + 8];
            #pragma unroll
            for (int nt = 0; nt < 4; nt++) {
                MMA_BF16(acc[mt][nt], ah0, ah1, ah2, ah3, bh[nt][0], bh[nt][1]);
                MMA_BF16(acc[mt][nt], ah0, ah1, ah2, ah3, bl[nt][0], bl[nt][1]);
                MMA_BF16(acc[mt][nt], al0, al1, al2, al3, bh[nt][0], bh[nt][1]);
            }
        }
    }
    __syncthreads();

    float* Ds = (float*)smem;
    #pragma unroll
    for (int mt = 0; mt < 4; mt++) {
        int r0 = wm * 64 + mt * 16 + gr;
        #pragma unroll
        for (int nt = 0; nt < 4; nt++) {
            int c0 = wn * 32 + nt * 8 + 2 * tg;
            Ds[r0 * 132 + c0]           = acc[mt][nt][0];
            Ds[r0 * 132 + c0 + 1]       = acc[mt][nt][1];
            Ds[(r0 + 8) * 132 + c0]     = acc[mt][nt][2];
            Ds[(r0 + 8) * 132 + c0 + 1] = acc[mt][nt][3];
        }
    }
    __syncthreads();

    const int c4 = (tid & 31) * 4;
    float4 bo = *(const float4*)&bout[n0 + c4];
    #pragma unroll
    for (int it = 0; it < 16; it++) {
        int r = (tid >> 5) + it * 8;
        float4 v = *(const float4*)&Ds[r * 132 + c4];
        v.x += bo.x; v.y += bo.y; v.z += bo.z; v.w += bo.w;
        *(float4*)&out[((size_t)r * NSTEP + step) * Vq + n0 + c4] = v;
    }
}

// ============ trap sentinel (should never fire now) =======================
__global__ void k_trap() { __trap(); }

// ============================== launcher ==================================
extern "C" void kernel_launch(void* const* d_in, const int* in_sizes, int n_in,
                              void* d_out, int out_size)
{
    static const int SZ[21] = {65536, 2048, 1024000, 6144, 12288, 192, 192,
                               6144, 12288, 192, 192, 16384, 128, 16384, 128,
                               61440, 49152, 384, 384, 4096000, 32000};
    bool ok = (n_in == 21);
    if (ok) for (int i = 0; i < 21; i++) if (in_sizes[i] != SZ[i]) { ok = false; break; }
    if (!ok) { k_trap<<<1, 1>>>(); return; }

    const int*   inputs  = (const int*)  d_in[0];
    const int*   targets = (const int*)  d_in[1];
    const float* emb     = (const float*)d_in[2];
    const float* W_ih_f  = (const float*)d_in[3];
    const float* W_hh_f  = (const float*)d_in[4];
    const float* b_ih_f  = (const float*)d_in[5];
    const float* b_hh_f  = (const float*)d_in[6];
    const float* W_ih_b  = (const float*)d_in[7];
    const float* W_hh_b  = (const float*)d_in[8];
    const float* b_ih_b  = (const float*)d_in[9];
    const float* b_hh_b  = (const float*)d_in[10];
    const float* W1      = (const float*)d_in[11];
    const float* b1      = (const float*)d_in[12];
    const float* W2      = (const float*)d_in[13];
    const float* b2      = (const float*)d_in[14];
    const float* W_ih_d  = (const float*)d_in[15];
    const float* W_hh_d  = (const float*)d_in[16];
    const float* b_ih_d  = (const float*)d_in[17];
    const float* b_hh_d  = (const float*)d_in[18];
    const float* W_out   = (const float*)d_in[19];
    const float* b_out   = (const float*)d_in[20];
    float* out = (float*)d_out;

    // one-time resources (host-side objects, no device memory)
    static cudaStream_t s1 = nullptr;
    static cudaEvent_t ev_fork, ev_dec[NSTEP], ev_join;
    if (!s1) {
        cudaStreamCreateWithFlags(&s1, cudaStreamNonBlocking);
        cudaEventCreateWithFlags(&ev_fork, cudaEventDisableTiming);
        cudaEventCreateWithFlags(&ev_join, cudaEventDisableTiming);
        for (int i = 0; i < NSTEP; i++)
            cudaEventCreateWithFlags(&ev_dec[i], cudaEventDisableTiming);
        cudaFuncSetAttribute(k_logits_bmma,
                             cudaFuncAttributeMaxDynamicSharedMemorySize, SMEM_MM);
    }

    // main chain (legacy stream): gi -> enc -> c2 -> gate -> dec steps
    k_gi  <<<dim3(3, 512), 256>>>(inputs, emb, W_ih_f, W_ih_b, b_ih_f, b_ih_b);
    cudaEventRecord(ev_fork, 0);
    cudaStreamWaitEvent(s1, ev_fork, 0);
    k_split_w<<<(Vq * Hq + 255) / 256, 256, 0, s1>>>(W_out);  // overlaps enc

    k_enc <<<256, 192>>>(W_hh_f, W_hh_b, b_hh_f, b_hh_b);
    k_c2  <<<128, 128>>>(W2, b1, b2);
    k_gate<<<dim3(1, 512), 256>>>(W1);

    for (int step = 0; step < NSTEP; step++) {
        k_dec_step<<<128, 512>>>(emb, targets, W_ih_d, W_hh_d,
                                 b_ih_d, b_hh_d, step);
        cudaEventRecord(ev_dec[step], 0);
        cudaStreamWaitEvent(s1, ev_dec[step], 0);
        k_logits_bmma<<<250, 256, SMEM_MM, s1>>>(b_out, out, step);
    }
    cudaEventRecord(ev_join, s1);
    cudaStreamWaitEvent(0, ev_join, 0);
}